// round 1
// baseline (speedup 1.0000x reference)
#include <cuda_runtime.h>
#include <cuda_bf16.h>
#include <math.h>
#include <stdint.h>

// ---------------- problem constants ----------------
#define N_NODES   19385
#define N_EDGES   1200000
#define GNN_DIM   256
#define HEAD_DIM  512
#define EXPAND    4
#define N_CLASSES 3
#define N_GENES   6640
#define N_RES     6
#define BATCH     2048
#define FF_DIM    (HEAD_DIM * EXPAND)   // 2048
#define BIL_DIM   (N_CLASSES * HEAD_DIM) // 1536

// ---------------- scratch (static device allocations) ----------------
__device__ float         g_aggr[(size_t)N_NODES * GNN_DIM];     // ~19.8 MB
__device__ unsigned char g_needed[N_NODES];
__device__ float         g_Wc1[GNN_DIM * GNN_DIM];
__device__ float         g_Wc2[GNN_DIM * GNN_DIM];
__device__ float         g_bc[GNN_DIM];
__device__ float         g_pert[(size_t)BATCH * GNN_DIM];
__device__ float         g_h[(size_t)BATCH * HEAD_DIM];
__device__ float         g_xn[(size_t)BATCH * HEAD_DIM];
__device__ float         g_act[(size_t)BATCH * FF_DIM];         // 16.8 MB
__device__ float         g_proj[(size_t)BATCH * BIL_DIM];

// ---------------- helpers ----------------
__device__ __forceinline__ float gelu_exact(float v) {
    return 0.5f * v * (1.0f + erff(v * 0.70710678118654752f));
}

// ---------------- zero scratch ----------------
__global__ void zero_kernel() {
    size_t stride = (size_t)gridDim.x * blockDim.x;
    size_t tid = (size_t)blockIdx.x * blockDim.x + threadIdx.x;
    size_t total4 = (size_t)N_NODES * (GNN_DIM / 4);
    float4* a4 = reinterpret_cast<float4*>(g_aggr);
    for (size_t i = tid; i < total4; i += stride)
        a4[i] = make_float4(0.f, 0.f, 0.f, 0.f);
    for (size_t i = tid; i < N_NODES; i += stride)
        g_needed[i] = 0;
}

// ---------------- mark needed nodes ----------------
__global__ void mark_kernel(const int* __restrict__ idx) {
    int b = blockIdx.x * blockDim.x + threadIdx.x;
    if (b < BATCH) {
        int n = idx[b];
        if (n >= 0) g_needed[n] = 1;
    }
}

// ---------------- filtered edge scatter-add ----------------
// warp handles 32 edges: ballot on needed[dst], cooperative 256-float
// gather/scale/atomic-add for each accepted edge.
__global__ void edge_kernel(const int* __restrict__ ei, const float* __restrict__ ew,
                            const float* __restrict__ x0) {
    const int lane = threadIdx.x & 31;
    const int warp = (blockIdx.x * blockDim.x + threadIdx.x) >> 5;
    const int e0 = warp * 32;
    if (e0 >= N_EDGES) return;
    const int e = e0 + lane;
    int d = 0, s = 0; float w = 0.f;
    bool ok = false;
    if (e < N_EDGES) {
        d = ei[N_EDGES + e];                 // dst row
        ok = (g_needed[d] != 0);
        if (ok) { s = ei[e]; w = ew[e]; }    // src, weight
    }
    unsigned mask = __ballot_sync(0xffffffffu, ok);
    while (mask) {
        int b = __ffs(mask) - 1; mask &= (mask - 1);
        int   ss = __shfl_sync(0xffffffffu, s, b);
        int   dd = __shfl_sync(0xffffffffu, d, b);
        float ww = __shfl_sync(0xffffffffu, w, b);
        const float4* xr = reinterpret_cast<const float4*>(x0 + (size_t)ss * GNN_DIM);
        float* ar = g_aggr + (size_t)dd * GNN_DIM;
        #pragma unroll
        for (int i = 0; i < 2; i++) {
            int c = lane + i * 32;           // float4 index 0..63
            float4 v = xr[c];
            atomicAdd(ar + c * 4 + 0, v.x * ww);
            atomicAdd(ar + c * 4 + 1, v.y * ww);
            atomicAdd(ar + c * 4 + 2, v.z * ww);
            atomicAdd(ar + c * 4 + 3, v.w * ww);
        }
    }
}

// ---------------- fold message-passing weights:
// Wc1 = (W_root + I) @ W_post ; Wc2 = W_nbr @ W_post ----------------
__global__ void wc_kernel(const float* __restrict__ Wr, const float* __restrict__ Wn,
                          const float* __restrict__ Wp) {
    int i = blockIdx.x;       // row
    int j = threadIdx.x;      // col
    __shared__ float r[GNN_DIM], nn[GNN_DIM];
    r[j]  = Wr[i * GNN_DIM + j] + (i == j ? 1.f : 0.f);
    nn[j] = Wn[i * GNN_DIM + j];
    __syncthreads();
    float a1 = 0.f, a2 = 0.f;
    #pragma unroll 4
    for (int k = 0; k < GNN_DIM; k++) {
        float wp = Wp[k * GNN_DIM + j];
        a1 += r[k]  * wp;
        a2 += nn[k] * wp;
    }
    g_Wc1[i * GNN_DIM + j] = a1;
    g_Wc2[i * GNN_DIM + j] = a2;
}

__global__ void bc_kernel(const float* __restrict__ bmp, const float* __restrict__ Wp,
                          const float* __restrict__ bpost) {
    int j = threadIdx.x;
    float a = bpost[j];
    #pragma unroll 4
    for (int k = 0; k < GNN_DIM; k++)
        a += bmp[k] * Wp[k * GNN_DIM + j];
    g_bc[j] = a;
}

// ---------------- per-batch-row node transform + fallback ----------------
// pert[b] = x0[n]@Wc1 + aggr[n]@Wc2 + bc   (or fallback_emb if n<0)
__global__ void pert_kernel(const int* __restrict__ idx, const float* __restrict__ x0,
                            const float* __restrict__ fb) {
    constexpr int RPB = 8;
    __shared__ float xr[RPB][GNN_DIM];
    __shared__ float ar[RPB][GNN_DIM];
    __shared__ int   ns[RPB];
    int j = threadIdx.x;
    int b0 = blockIdx.x * RPB;
    if (j < RPB) ns[j] = idx[b0 + j];
    __syncthreads();
    #pragma unroll
    for (int r = 0; r < RPB; r++) {
        int n = ns[r]; int sn = (n < 0) ? 0 : n;
        xr[r][j] = x0[(size_t)sn * GNN_DIM + j];
        ar[r][j] = g_aggr[(size_t)sn * GNN_DIM + j];
    }
    __syncthreads();
    float acc[RPB];
    #pragma unroll
    for (int r = 0; r < RPB; r++) acc[r] = g_bc[j];
    for (int k = 0; k < GNN_DIM; k++) {
        float w1 = g_Wc1[k * GNN_DIM + j];
        float w2 = g_Wc2[k * GNN_DIM + j];
        #pragma unroll
        for (int r = 0; r < RPB; r++)
            acc[r] += xr[r][k] * w1 + ar[r][k] * w2;
    }
    float fbj = fb[j];
    #pragma unroll
    for (int r = 0; r < RPB; r++)
        g_pert[(size_t)(b0 + r) * GNN_DIM + j] = (ns[r] >= 0) ? acc[r] : fbj;
}

// ---------------- layernorm ----------------
__global__ void ln_kernel(const float* __restrict__ h, const float* __restrict__ g,
                          const float* __restrict__ bb, float* __restrict__ out) {
    int row = blockIdx.x;
    const float* x = h + (size_t)row * HEAD_DIM;
    int tid = threadIdx.x;   // 128
    float v[4]; float s = 0.f, s2 = 0.f;
    #pragma unroll
    for (int i = 0; i < 4; i++) {
        v[i] = x[tid + i * 128];
        s += v[i]; s2 += v[i] * v[i];
    }
    #pragma unroll
    for (int o = 16; o; o >>= 1) {
        s  += __shfl_down_sync(0xffffffffu, s, o);
        s2 += __shfl_down_sync(0xffffffffu, s2, o);
    }
    __shared__ float ss[4], ss2[4];
    if ((tid & 31) == 0) { ss[tid >> 5] = s; ss2[tid >> 5] = s2; }
    __syncthreads();
    s  = ss[0] + ss[1] + ss[2] + ss[3];
    s2 = ss2[0] + ss2[1] + ss2[2] + ss2[3];
    float mu  = s * (1.f / HEAD_DIM);
    float var = s2 * (1.f / HEAD_DIM) - mu * mu;
    float rs  = rsqrtf(var + 1e-5f);
    float* o = out + (size_t)row * HEAD_DIM;
    #pragma unroll
    for (int i = 0; i < 4; i++) {
        int j = tid + i * 128;
        o[j] = (v[i] - mu) * rs * g[j] + bb[j];
    }
}

// ---------------- generic tiled SGEMM ----------------
// C[M,N] = A[M,K] @ B   (B is [K,N] row-major, or [N,K] if TRANSB)
// epilogue: +bias[n] (BIAS), gelu (GELU), += old C (RESID)
constexpr int BM = 128, BN = 128, BK = 8, TM = 8, TN = 8;

template<bool TRANSB, bool BIAS, bool GELU, bool RESID>
__global__ void sgemm_kernel(int M, int N, int K,
                             const float* __restrict__ A, const float* __restrict__ B,
                             const float* __restrict__ bias, float* __restrict__ C) {
    __shared__ float As[BK][BM + 4];
    __shared__ float Bs[BK][BN + 4];
    const int tid  = threadIdx.x;                  // 256 threads
    const int crow = blockIdx.y * BM;
    const int ccol = blockIdx.x * BN;
    const int tr = tid / (BN / TN);                // 0..15
    const int tc = tid % (BN / TN);                // 0..15
    const int arow = tid >> 1;                     // 0..127
    const int acol = (tid & 1) * 4;                // 0 or 4
    const int brow = tid >> 5;                     // 0..7
    const int bcol = (tid & 31) * 4;               // 0..124

    float acc[TM][TN];
    #pragma unroll
    for (int i = 0; i < TM; i++)
        #pragma unroll
        for (int j = 0; j < TN; j++) acc[i][j] = 0.f;

    for (int k0 = 0; k0 < K; k0 += BK) {
        // A tile (guarded on M)
        {
            int m = crow + arow;
            float4 v = make_float4(0.f, 0.f, 0.f, 0.f);
            if (m < M) v = *reinterpret_cast<const float4*>(A + (size_t)m * K + k0 + acol);
            As[acol + 0][arow] = v.x; As[acol + 1][arow] = v.y;
            As[acol + 2][arow] = v.z; As[acol + 3][arow] = v.w;
        }
        if (!TRANSB) {
            int n = ccol + bcol;
            float4 v = make_float4(0.f, 0.f, 0.f, 0.f);
            if (n + 3 < N) v = *reinterpret_cast<const float4*>(B + (size_t)(k0 + brow) * N + n);
            Bs[brow][bcol + 0] = v.x; Bs[brow][bcol + 1] = v.y;
            Bs[brow][bcol + 2] = v.z; Bs[brow][bcol + 3] = v.w;
        } else {
            int n = ccol + arow;
            float4 v = make_float4(0.f, 0.f, 0.f, 0.f);
            if (n < N) v = *reinterpret_cast<const float4*>(B + (size_t)n * K + k0 + acol);
            Bs[acol + 0][arow] = v.x; Bs[acol + 1][arow] = v.y;
            Bs[acol + 2][arow] = v.z; Bs[acol + 3][arow] = v.w;
        }
        __syncthreads();

        #pragma unroll
        for (int d = 0; d < BK; d++) {
            float regM[TM], regN[TN];
            float4 m0 = *reinterpret_cast<const float4*>(&As[d][tr * TM]);
            float4 m1 = *reinterpret_cast<const float4*>(&As[d][tr * TM + 4]);
            regM[0] = m0.x; regM[1] = m0.y; regM[2] = m0.z; regM[3] = m0.w;
            regM[4] = m1.x; regM[5] = m1.y; regM[6] = m1.z; regM[7] = m1.w;
            float4 n0 = *reinterpret_cast<const float4*>(&Bs[d][tc * TN]);
            float4 n1 = *reinterpret_cast<const float4*>(&Bs[d][tc * TN + 4]);
            regN[0] = n0.x; regN[1] = n0.y; regN[2] = n0.z; regN[3] = n0.w;
            regN[4] = n1.x; regN[5] = n1.y; regN[6] = n1.z; regN[7] = n1.w;
            #pragma unroll
            for (int i = 0; i < TM; i++)
                #pragma unroll
                for (int j = 0; j < TN; j++)
                    acc[i][j] += regM[i] * regN[j];
        }
        __syncthreads();
    }

    #pragma unroll
    for (int i = 0; i < TM; i++) {
        int m = crow + tr * TM + i;
        if (m >= M) continue;
        #pragma unroll
        for (int j = 0; j < TN; j++) {
            int n = ccol + tc * TN + j;
            if (n >= N) continue;
            float v = acc[i][j];
            if (BIAS) v += bias[n];
            if (GELU) v = gelu_exact(v);
            float* p = C + (size_t)m * N + n;
            if (RESID) v += *p;
            *p = v;
        }
    }
}

// ---------------- launch ----------------
extern "C" void kernel_launch(void* const* d_in, const int* in_sizes, int n_in,
                              void* d_out, int out_size) {
    const int*   node_idx  = (const int*)  d_in[0];
    const int*   edge_idx  = (const int*)  d_in[1];
    const float* edge_w    = (const float*)d_in[2];
    const float* frozen    = (const float*)d_in[3];
    const float* W_root    = (const float*)d_in[4];
    const float* W_nbr     = (const float*)d_in[5];
    const float* b_mp      = (const float*)d_in[6];
    const float* W_post    = (const float*)d_in[7];
    const float* b_post    = (const float*)d_in[8];
    const float* fallback  = (const float*)d_in[9];
    const float* W_in      = (const float*)d_in[10];
    const float* b_in      = (const float*)d_in[11];
    const float* ln_g      = (const float*)d_in[12];
    const float* ln_b      = (const float*)d_in[13];
    const float* W1        = (const float*)d_in[14];
    const float* b1        = (const float*)d_in[15];
    const float* W2        = (const float*)d_in[16];
    const float* W_bil     = (const float*)d_in[17];
    const float* out_emb   = (const float*)d_in[18];
    float*       logits    = (float*)d_out;

    float *p_pert, *p_h, *p_xn, *p_act, *p_proj;
    cudaGetSymbolAddress((void**)&p_pert, g_pert);
    cudaGetSymbolAddress((void**)&p_h,    g_h);
    cudaGetSymbolAddress((void**)&p_xn,   g_xn);
    cudaGetSymbolAddress((void**)&p_act,  g_act);
    cudaGetSymbolAddress((void**)&p_proj, g_proj);

    // --- graph phase ---
    zero_kernel<<<1024, 256>>>();
    mark_kernel<<<(BATCH + 255) / 256, 256>>>(node_idx);
    {
        int warps = (N_EDGES + 31) / 32;
        int blocks = (warps + 7) / 8;        // 8 warps / block
        edge_kernel<<<blocks, 256>>>(edge_idx, edge_w, frozen);
    }
    wc_kernel<<<GNN_DIM, GNN_DIM>>>(W_root, W_nbr, W_post);
    bc_kernel<<<1, GNN_DIM>>>(b_mp, W_post, b_post);
    pert_kernel<<<BATCH / 8, GNN_DIM>>>(node_idx, frozen, fallback);

    // --- dense head ---
    // h = gelu(pert @ W_in + b_in)
    {
        dim3 grid(HEAD_DIM / BN, BATCH / BM);
        sgemm_kernel<false, true, true, false><<<grid, 256>>>(
            BATCH, HEAD_DIM, GNN_DIM, p_pert, W_in, b_in, p_h);
    }
    // 6 residual MLP blocks
    for (int i = 0; i < N_RES; i++) {
        ln_kernel<<<BATCH, 128>>>(p_h, ln_g + (size_t)i * HEAD_DIM,
                                  ln_b + (size_t)i * HEAD_DIM, p_xn);
        dim3 g1(FF_DIM / BN, BATCH / BM);
        sgemm_kernel<false, true, true, false><<<g1, 256>>>(
            BATCH, FF_DIM, HEAD_DIM, p_xn, W1 + (size_t)i * HEAD_DIM * FF_DIM,
            b1 + (size_t)i * FF_DIM, p_act);
        dim3 g2(HEAD_DIM / BN, BATCH / BM);
        sgemm_kernel<false, false, false, true><<<g2, 256>>>(
            BATCH, HEAD_DIM, FF_DIM, p_act, W2 + (size_t)i * FF_DIM * HEAD_DIM,
            nullptr, p_h);
    }
    // proj = h @ W_bil
    {
        dim3 grid(BIL_DIM / BN, BATCH / BM);
        sgemm_kernel<false, false, false, false><<<grid, 256>>>(
            BATCH, BIL_DIM, HEAD_DIM, p_h, W_bil, nullptr, p_proj);
    }
    // logits = reshape(proj,[B*3,512]) @ out_emb^T
    {
        dim3 grid((N_GENES + BN - 1) / BN, (BATCH * N_CLASSES) / BM);
        sgemm_kernel<true, false, false, false><<<grid, 256>>>(
            BATCH * N_CLASSES, N_GENES, HEAD_DIM, p_proj, out_emb, nullptr, logits);
    }
}

// round 3
// speedup vs baseline: 2.3477x; 2.3477x over previous
#include <cuda_runtime.h>
#include <cuda_bf16.h>
#include <math.h>
#include <stdint.h>

// ---------------- problem constants ----------------
#define N_NODES   19385
#define N_EDGES   1200000
#define GNN_DIM   256
#define HEAD_DIM  512
#define EXPAND    4
#define N_CLASSES 3
#define N_GENES   6640
#define N_RES     6
#define BATCH     2048
#define FF_DIM    (HEAD_DIM * EXPAND)    // 2048
#define BIL_DIM   (N_CLASSES * HEAD_DIM) // 1536

// ---------------- scratch (static device allocations) ----------------
__device__ float         g_aggr[(size_t)N_NODES * GNN_DIM];     // ~19.8 MB
__device__ unsigned char g_needed[N_NODES];
__device__ float         g_Wc1[GNN_DIM * GNN_DIM];
__device__ float         g_Wc2[GNN_DIM * GNN_DIM];
__device__ float         g_bc[GNN_DIM];
__device__ float         g_pert[(size_t)BATCH * GNN_DIM];
__device__ float         g_h[(size_t)BATCH * HEAD_DIM];
__device__ float         g_xn[(size_t)BATCH * HEAD_DIM];
__device__ float         g_act[(size_t)BATCH * FF_DIM];         // 16.8 MB
__device__ float         g_proj[(size_t)BATCH * BIL_DIM];

// ---------------- helpers ----------------
__device__ __forceinline__ float gelu_exact(float v) {
    return 0.5f * v * (1.0f + erff(v * 0.70710678118654752f));
}

__device__ __forceinline__ float to_tf32(float x) {
    uint32_t u;
    asm("cvt.rna.tf32.f32 %0, %1;" : "=r"(u) : "f"(x));
    return __uint_as_float(u);
}

// ---------------- zero scratch ----------------
__global__ void zero_kernel() {
    size_t stride = (size_t)gridDim.x * blockDim.x;
    size_t tid = (size_t)blockIdx.x * blockDim.x + threadIdx.x;
    size_t total4 = (size_t)N_NODES * (GNN_DIM / 4);
    float4* a4 = reinterpret_cast<float4*>(g_aggr);
    for (size_t i = tid; i < total4; i += stride)
        a4[i] = make_float4(0.f, 0.f, 0.f, 0.f);
    for (size_t i = tid; i < N_NODES; i += stride)
        g_needed[i] = 0;
}

// ---------------- mark needed nodes ----------------
__global__ void mark_kernel(const int* __restrict__ idx) {
    int b = blockIdx.x * blockDim.x + threadIdx.x;
    if (b < BATCH) {
        int n = idx[b];
        if (n >= 0) g_needed[n] = 1;
    }
}

// ---------------- filtered edge scatter-add ----------------
__global__ void edge_kernel(const int* __restrict__ ei, const float* __restrict__ ew,
                            const float* __restrict__ x0) {
    const int lane = threadIdx.x & 31;
    const int warp = (blockIdx.x * blockDim.x + threadIdx.x) >> 5;
    const int e0 = warp * 32;
    if (e0 >= N_EDGES) return;
    const int e = e0 + lane;
    int d = 0, s = 0; float w = 0.f;
    bool ok = false;
    if (e < N_EDGES) {
        d = ei[N_EDGES + e];                 // dst row
        ok = (g_needed[d] != 0);
        if (ok) { s = ei[e]; w = ew[e]; }    // src, weight
    }
    unsigned mask = __ballot_sync(0xffffffffu, ok);
    while (mask) {
        int b = __ffs(mask) - 1; mask &= (mask - 1);
        int   ss = __shfl_sync(0xffffffffu, s, b);
        int   dd = __shfl_sync(0xffffffffu, d, b);
        float ww = __shfl_sync(0xffffffffu, w, b);
        const float4* xr = reinterpret_cast<const float4*>(x0 + (size_t)ss * GNN_DIM);
        float* ar = g_aggr + (size_t)dd * GNN_DIM;
        #pragma unroll
        for (int i = 0; i < 2; i++) {
            int c = lane + i * 32;           // float4 index 0..63
            float4 v = xr[c];
            atomicAdd(ar + c * 4 + 0, v.x * ww);
            atomicAdd(ar + c * 4 + 1, v.y * ww);
            atomicAdd(ar + c * 4 + 2, v.z * ww);
            atomicAdd(ar + c * 4 + 3, v.w * ww);
        }
    }
}

// ---------------- fold message-passing weights ----------------
__global__ void wc_kernel(const float* __restrict__ Wr, const float* __restrict__ Wn,
                          const float* __restrict__ Wp) {
    int i = blockIdx.x;       // row
    int j = threadIdx.x;      // col
    __shared__ float r[GNN_DIM], nn[GNN_DIM];
    r[j]  = Wr[i * GNN_DIM + j] + (i == j ? 1.f : 0.f);
    nn[j] = Wn[i * GNN_DIM + j];
    __syncthreads();
    float a1 = 0.f, a2 = 0.f;
    #pragma unroll 4
    for (int k = 0; k < GNN_DIM; k++) {
        float wp = Wp[k * GNN_DIM + j];
        a1 += r[k]  * wp;
        a2 += nn[k] * wp;
    }
    g_Wc1[i * GNN_DIM + j] = a1;
    g_Wc2[i * GNN_DIM + j] = a2;
}

__global__ void bc_kernel(const float* __restrict__ bmp, const float* __restrict__ Wp,
                          const float* __restrict__ bpost) {
    int j = threadIdx.x;
    float a = bpost[j];
    #pragma unroll 4
    for (int k = 0; k < GNN_DIM; k++)
        a += bmp[k] * Wp[k * GNN_DIM + j];
    g_bc[j] = a;
}

// ---------------- per-batch-row node transform + fallback ----------------
__global__ void pert_kernel(const int* __restrict__ idx, const float* __restrict__ x0,
                            const float* __restrict__ fb) {
    constexpr int RPB = 8;
    __shared__ float xr[RPB][GNN_DIM];
    __shared__ float ar[RPB][GNN_DIM];
    __shared__ int   ns[RPB];
    int j = threadIdx.x;
    int b0 = blockIdx.x * RPB;
    if (j < RPB) ns[j] = idx[b0 + j];
    __syncthreads();
    #pragma unroll
    for (int r = 0; r < RPB; r++) {
        int n = ns[r]; int sn = (n < 0) ? 0 : n;
        xr[r][j] = x0[(size_t)sn * GNN_DIM + j];
        ar[r][j] = g_aggr[(size_t)sn * GNN_DIM + j];
    }
    __syncthreads();
    float acc[RPB];
    #pragma unroll
    for (int r = 0; r < RPB; r++) acc[r] = g_bc[j];
    for (int k = 0; k < GNN_DIM; k++) {
        float w1 = g_Wc1[k * GNN_DIM + j];
        float w2 = g_Wc2[k * GNN_DIM + j];
        #pragma unroll
        for (int r = 0; r < RPB; r++)
            acc[r] += xr[r][k] * w1 + ar[r][k] * w2;
    }
    float fbj = fb[j];
    #pragma unroll
    for (int r = 0; r < RPB; r++)
        g_pert[(size_t)(b0 + r) * GNN_DIM + j] = (ns[r] >= 0) ? acc[r] : fbj;
}

// ---------------- layernorm ----------------
__global__ void ln_kernel(const float* __restrict__ h, const float* __restrict__ g,
                          const float* __restrict__ bb, float* __restrict__ out) {
    int row = blockIdx.x;
    const float* x = h + (size_t)row * HEAD_DIM;
    int tid = threadIdx.x;   // 128
    float v[4]; float s = 0.f, s2 = 0.f;
    #pragma unroll
    for (int i = 0; i < 4; i++) {
        v[i] = x[tid + i * 128];
        s += v[i]; s2 += v[i] * v[i];
    }
    #pragma unroll
    for (int o = 16; o; o >>= 1) {
        s  += __shfl_down_sync(0xffffffffu, s, o);
        s2 += __shfl_down_sync(0xffffffffu, s2, o);
    }
    __shared__ float ss[4], ss2[4];
    if ((tid & 31) == 0) { ss[tid >> 5] = s; ss2[tid >> 5] = s2; }
    __syncthreads();
    s  = ss[0] + ss[1] + ss[2] + ss[3];
    s2 = ss2[0] + ss2[1] + ss2[2] + ss2[3];
    float mu  = s * (1.f / HEAD_DIM);
    float var = s2 * (1.f / HEAD_DIM) - mu * mu;
    float rs  = rsqrtf(var + 1e-5f);
    float* o = out + (size_t)row * HEAD_DIM;
    #pragma unroll
    for (int i = 0; i < 4; i++) {
        int j = tid + i * 128;
        o[j] = (v[i] - mu) * rs * g[j] + bb[j];
    }
}

// ================= TF32 tensor-core GEMM =================
// C[M,N] = A[M,K] @ B   (B is [K,N] row-major, or [N,K] if TRANSB)
// Block 128x128xBK16, 8 warps (2x4), warp tile 64x32, mma m16n8k8 tf32.
// Requirements held by all call sites: M % 128 == 0, K % 16 == 0.
// N may be ragged (logits GEMM): guarded on B loads (TRANSB) and C stores.
constexpr int BM = 128, BN = 128, BK = 16;

template<bool TRANSB, bool BIAS, bool GELU, bool RESID>
__global__ void __launch_bounds__(256) gemm_tc(int M, int N, int K,
                                               const float* __restrict__ A,
                                               const float* __restrict__ B,
                                               const float* __restrict__ bias,
                                               float* __restrict__ C) {
    __shared__ float As[BM][BK + 4];   // A[m][k], tf32-rounded
    __shared__ float Bs[BK][BN + 4];   // B[k][n], tf32-rounded

    const int tid  = threadIdx.x;
    const int lane = tid & 31;
    const int warp = tid >> 5;
    const int crow = blockIdx.y * BM;
    const int ccol = blockIdx.x * BN;
    const int warpM = (warp >> 2) * 64;   // 0 or 64
    const int warpN = (warp & 3) * 32;    // 0,32,64,96
    const int r = lane >> 2;              // 0..7
    const int c = lane & 3;               // 0..3

    float acc[4][4][4];
    #pragma unroll
    for (int mt = 0; mt < 4; mt++)
        #pragma unroll
        for (int nt = 0; nt < 4; nt++)
            #pragma unroll
            for (int i = 0; i < 4; i++) acc[mt][nt][i] = 0.f;

    for (int k0 = 0; k0 < K; k0 += BK) {
        // ---- load A tile: 128 x 16, float4 along k ----
        #pragma unroll
        for (int i = 0; i < 2; i++) {
            int f = tid + i * 256;            // 0..511
            int row = f >> 2;                 // 0..127
            int col = (f & 3) * 4;            // 0,4,8,12
            float4 v = *reinterpret_cast<const float4*>(
                A + (size_t)(crow + row) * K + k0 + col);
            float4* dst = reinterpret_cast<float4*>(&As[row][col]);
            *dst = make_float4(to_tf32(v.x), to_tf32(v.y), to_tf32(v.z), to_tf32(v.w));
        }
        // ---- load B tile: 16 x 128 ----
        if (!TRANSB) {
            #pragma unroll
            for (int i = 0; i < 2; i++) {
                int f = tid + i * 256;
                int row = f >> 5;             // 0..15 (k)
                int col = (f & 31) * 4;       // 0..124 (n)
                float4 v = *reinterpret_cast<const float4*>(
                    B + (size_t)(k0 + row) * N + ccol + col);
                float4* dst = reinterpret_cast<float4*>(&Bs[row][col]);
                *dst = make_float4(to_tf32(v.x), to_tf32(v.y), to_tf32(v.z), to_tf32(v.w));
            }
        } else {
            // B is [N,K]; Bs[k][n] = B[ccol+n][k0+k]; transpose on store
            #pragma unroll
            for (int i = 0; i < 2; i++) {
                int f = tid + i * 256;
                int n  = f >> 2;              // 0..127
                int kb = (f & 3) * 4;         // 0,4,8,12
                float4 v = make_float4(0.f, 0.f, 0.f, 0.f);
                if (ccol + n < N)
                    v = *reinterpret_cast<const float4*>(
                        B + (size_t)(ccol + n) * K + k0 + kb);
                Bs[kb + 0][n] = to_tf32(v.x);
                Bs[kb + 1][n] = to_tf32(v.y);
                Bs[kb + 2][n] = to_tf32(v.z);
                Bs[kb + 3][n] = to_tf32(v.w);
            }
        }
        __syncthreads();

        // ---- compute: 2 k-steps of 8 ----
        #pragma unroll
        for (int ks = 0; ks < 2; ks++) {
            const int kb = ks * 8;
            uint32_t a[4][4], b[4][2];
            #pragma unroll
            for (int mt = 0; mt < 4; mt++) {
                int m0 = warpM + mt * 16;
                a[mt][0] = __float_as_uint(As[m0 + r    ][kb + c    ]);
                a[mt][1] = __float_as_uint(As[m0 + 8 + r][kb + c    ]);
                a[mt][2] = __float_as_uint(As[m0 + r    ][kb + c + 4]);
                a[mt][3] = __float_as_uint(As[m0 + 8 + r][kb + c + 4]);
            }
            #pragma unroll
            for (int nt = 0; nt < 4; nt++) {
                int n0 = warpN + nt * 8;
                b[nt][0] = __float_as_uint(Bs[kb + c    ][n0 + r]);
                b[nt][1] = __float_as_uint(Bs[kb + c + 4][n0 + r]);
            }
            #pragma unroll
            for (int mt = 0; mt < 4; mt++)
                #pragma unroll
                for (int nt = 0; nt < 4; nt++) {
                    asm volatile(
                        "mma.sync.aligned.m16n8k8.row.col.f32.tf32.tf32.f32 "
                        "{%0,%1,%2,%3}, {%4,%5,%6,%7}, {%8,%9}, {%0,%1,%2,%3};\n"
                        : "+f"(acc[mt][nt][0]), "+f"(acc[mt][nt][1]),
                          "+f"(acc[mt][nt][2]), "+f"(acc[mt][nt][3])
                        : "r"(a[mt][0]), "r"(a[mt][1]), "r"(a[mt][2]), "r"(a[mt][3]),
                          "r"(b[nt][0]), "r"(b[nt][1]));
                }
        }
        __syncthreads();
    }

    // ---- epilogue ----
    #pragma unroll
    for (int mt = 0; mt < 4; mt++) {
        #pragma unroll
        for (int nt = 0; nt < 4; nt++) {
            int m0 = crow + warpM + mt * 16;
            int n0 = ccol + warpN + nt * 8;
            #pragma unroll
            for (int half = 0; half < 2; half++) {
                int m = m0 + r + half * 8;
                #pragma unroll
                for (int j = 0; j < 2; j++) {
                    int n = n0 + c * 2 + j;
                    if (n >= N) continue;
                    float v = acc[mt][nt][half * 2 + j];
                    if (BIAS) v += bias[n];
                    if (GELU) v = gelu_exact(v);
                    float* p = C + (size_t)m * N + n;
                    if (RESID) v += *p;
                    *p = v;
                }
            }
        }
    }
}

// ---------------- launch ----------------
extern "C" void kernel_launch(void* const* d_in, const int* in_sizes, int n_in,
                              void* d_out, int out_size) {
    const int*   node_idx  = (const int*)  d_in[0];
    const int*   edge_idx  = (const int*)  d_in[1];
    const float* edge_w    = (const float*)d_in[2];
    const float* frozen    = (const float*)d_in[3];
    const float* W_root    = (const float*)d_in[4];
    const float* W_nbr     = (const float*)d_in[5];
    const float* b_mp      = (const float*)d_in[6];
    const float* W_post    = (const float*)d_in[7];
    const float* b_post    = (const float*)d_in[8];
    const float* fallback  = (const float*)d_in[9];
    const float* W_in      = (const float*)d_in[10];
    const float* b_in      = (const float*)d_in[11];
    const float* ln_g      = (const float*)d_in[12];
    const float* ln_b      = (const float*)d_in[13];
    const float* W1        = (const float*)d_in[14];
    const float* b1        = (const float*)d_in[15];
    const float* W2        = (const float*)d_in[16];
    const float* W_bil     = (const float*)d_in[17];
    const float* out_emb   = (const float*)d_in[18];
    float*       logits    = (float*)d_out;

    float *p_pert, *p_h, *p_xn, *p_act, *p_proj;
    cudaGetSymbolAddress((void**)&p_pert, g_pert);
    cudaGetSymbolAddress((void**)&p_h,    g_h);
    cudaGetSymbolAddress((void**)&p_xn,   g_xn);
    cudaGetSymbolAddress((void**)&p_act,  g_act);
    cudaGetSymbolAddress((void**)&p_proj, g_proj);

    // --- graph phase ---
    zero_kernel<<<1024, 256>>>();
    mark_kernel<<<(BATCH + 255) / 256, 256>>>(node_idx);
    {
        int warps = (N_EDGES + 31) / 32;
        int blocks = (warps + 7) / 8;        // 8 warps / block
        edge_kernel<<<blocks, 256>>>(edge_idx, edge_w, frozen);
    }
    wc_kernel<<<GNN_DIM, GNN_DIM>>>(W_root, W_nbr, W_post);
    bc_kernel<<<1, GNN_DIM>>>(b_mp, W_post, b_post);
    pert_kernel<<<BATCH / 8, GNN_DIM>>>(node_idx, frozen, fallback);

    // --- dense head (TF32 tensor-core GEMMs) ---
    // h = gelu(pert @ W_in + b_in)
    {
        dim3 grid(HEAD_DIM / BN, BATCH / BM);
        gemm_tc<false, true, true, false><<<grid, 256>>>(
            BATCH, HEAD_DIM, GNN_DIM, p_pert, W_in, b_in, p_h);
    }
    // 6 residual MLP blocks
    for (int i = 0; i < N_RES; i++) {
        ln_kernel<<<BATCH, 128>>>(p_h, ln_g + (size_t)i * HEAD_DIM,
                                  ln_b + (size_t)i * HEAD_DIM, p_xn);
        dim3 g1(FF_DIM / BN, BATCH / BM);
        gemm_tc<false, true, true, false><<<g1, 256>>>(
            BATCH, FF_DIM, HEAD_DIM, p_xn, W1 + (size_t)i * HEAD_DIM * FF_DIM,
            b1 + (size_t)i * FF_DIM, p_act);
        dim3 g2(HEAD_DIM / BN, BATCH / BM);
        gemm_tc<false, false, false, true><<<g2, 256>>>(
            BATCH, HEAD_DIM, FF_DIM, p_act, W2 + (size_t)i * FF_DIM * HEAD_DIM,
            nullptr, p_h);
    }
    // proj = h @ W_bil
    {
        dim3 grid(BIL_DIM / BN, BATCH / BM);
        gemm_tc<false, false, false, false><<<grid, 256>>>(
            BATCH, BIL_DIM, HEAD_DIM, p_h, W_bil, nullptr, p_proj);
    }
    // logits = reshape(proj,[B*3,512]) @ out_emb^T
    {
        dim3 grid((N_GENES + BN - 1) / BN, (BATCH * N_CLASSES) / BM);
        gemm_tc<true, false, false, false><<<grid, 256>>>(
            BATCH * N_CLASSES, N_GENES, HEAD_DIM, p_proj, out_emb, nullptr, logits);
    }
}

// round 4
// speedup vs baseline: 2.8661x; 1.2208x over previous
#include <cuda_runtime.h>
#include <cuda_bf16.h>
#include <math.h>
#include <stdint.h>

// ---------------- problem constants ----------------
#define N_NODES   19385
#define N_EDGES   1200000
#define GNN_DIM   256
#define HEAD_DIM  512
#define EXPAND    4
#define N_CLASSES 3
#define N_GENES   6640
#define N_RES     6
#define BATCH     2048
#define FF_DIM    (HEAD_DIM * EXPAND)    // 2048
#define BIL_DIM   (N_CLASSES * HEAD_DIM) // 1536

// ---------------- fp32 scratch ----------------
__device__ float         g_aggr[(size_t)N_NODES * GNN_DIM];
__device__ unsigned char g_needed[N_NODES];
__device__ float         g_Wc1[GNN_DIM * GNN_DIM];
__device__ float         g_Wc2[GNN_DIM * GNN_DIM];
__device__ float         g_bc[GNN_DIM];
__device__ float         g_h[(size_t)BATCH * HEAD_DIM];

// ---------------- bf16 split scratch (hi/lo pairs) ----------------
__device__ __nv_bfloat16 g_perth[(size_t)BATCH * GNN_DIM];
__device__ __nv_bfloat16 g_pertl[(size_t)BATCH * GNN_DIM];
__device__ __nv_bfloat16 g_xnh[(size_t)BATCH * HEAD_DIM];
__device__ __nv_bfloat16 g_xnl[(size_t)BATCH * HEAD_DIM];
__device__ __nv_bfloat16 g_acth[(size_t)BATCH * FF_DIM];
__device__ __nv_bfloat16 g_actl[(size_t)BATCH * FF_DIM];
__device__ __nv_bfloat16 g_hsh[(size_t)BATCH * HEAD_DIM];
__device__ __nv_bfloat16 g_hsl[(size_t)BATCH * HEAD_DIM];
__device__ __nv_bfloat16 g_projh[(size_t)BATCH * BIL_DIM];
__device__ __nv_bfloat16 g_projl[(size_t)BATCH * BIL_DIM];
// weight splits
__device__ __nv_bfloat16 g_Winh[GNN_DIM * HEAD_DIM];
__device__ __nv_bfloat16 g_Winl[GNN_DIM * HEAD_DIM];
__device__ __nv_bfloat16 g_W1h[(size_t)N_RES * HEAD_DIM * FF_DIM];
__device__ __nv_bfloat16 g_W1l[(size_t)N_RES * HEAD_DIM * FF_DIM];
__device__ __nv_bfloat16 g_W2h[(size_t)N_RES * FF_DIM * HEAD_DIM];
__device__ __nv_bfloat16 g_W2l[(size_t)N_RES * FF_DIM * HEAD_DIM];
__device__ __nv_bfloat16 g_bilh[HEAD_DIM * BIL_DIM];
__device__ __nv_bfloat16 g_bill[HEAD_DIM * BIL_DIM];
__device__ __nv_bfloat16 g_oeh[(size_t)N_GENES * HEAD_DIM];
__device__ __nv_bfloat16 g_oel[(size_t)N_GENES * HEAD_DIM];

// ---------------- helpers ----------------
__device__ __forceinline__ float gelu_exact(float v) {
    return 0.5f * v * (1.0f + erff(v * 0.70710678118654752f));
}
__device__ __forceinline__ void split2(float x, __nv_bfloat16& h, __nv_bfloat16& l) {
    h = __float2bfloat16_rn(x);
    l = __float2bfloat16_rn(x - __bfloat162float(h));
}
__device__ __forceinline__ uint32_t smem_u32(const void* p) {
    return (uint32_t)__cvta_generic_to_shared(p);
}
__device__ __forceinline__ void cp16(uint32_t dst, const void* src, bool pred) {
    int sz = pred ? 16 : 0;
    asm volatile("cp.async.cg.shared.global [%0], [%1], 16, %2;\n"
                 :: "r"(dst), "l"(src), "r"(sz));
}
__device__ __forceinline__ void ldm_x4(uint32_t* r, uint32_t addr) {
    asm volatile("ldmatrix.sync.aligned.m8n8.x4.shared.b16 {%0,%1,%2,%3}, [%4];"
                 : "=r"(r[0]), "=r"(r[1]), "=r"(r[2]), "=r"(r[3]) : "r"(addr));
}
__device__ __forceinline__ void ldm_x4_t(uint32_t* r, uint32_t addr) {
    asm volatile("ldmatrix.sync.aligned.m8n8.x4.trans.shared.b16 {%0,%1,%2,%3}, [%4];"
                 : "=r"(r[0]), "=r"(r[1]), "=r"(r[2]), "=r"(r[3]) : "r"(addr));
}
#define MMA_BF16(D, A, B)                                                   \
    asm volatile(                                                           \
        "mma.sync.aligned.m16n8k16.row.col.f32.bf16.bf16.f32 "              \
        "{%0,%1,%2,%3},{%4,%5,%6,%7},{%8,%9},{%0,%1,%2,%3};"                \
        : "+f"((D)[0]), "+f"((D)[1]), "+f"((D)[2]), "+f"((D)[3])            \
        : "r"((A)[0]), "r"((A)[1]), "r"((A)[2]), "r"((A)[3]),               \
          "r"((B)[0]), "r"((B)[1]))

// ---------------- zero scratch ----------------
__global__ void zero_kernel() {
    size_t stride = (size_t)gridDim.x * blockDim.x;
    size_t tid = (size_t)blockIdx.x * blockDim.x + threadIdx.x;
    size_t total4 = (size_t)N_NODES * (GNN_DIM / 4);
    float4* a4 = reinterpret_cast<float4*>(g_aggr);
    for (size_t i = tid; i < total4; i += stride)
        a4[i] = make_float4(0.f, 0.f, 0.f, 0.f);
    for (size_t i = tid; i < N_NODES; i += stride)
        g_needed[i] = 0;
}

__global__ void mark_kernel(const int* __restrict__ idx) {
    int b = blockIdx.x * blockDim.x + threadIdx.x;
    if (b < BATCH) {
        int n = idx[b];
        if (n >= 0) g_needed[n] = 1;
    }
}

// ---------------- filtered edge scatter-add (vectorized red) ----------------
__global__ void edge_kernel(const int* __restrict__ ei, const float* __restrict__ ew,
                            const float* __restrict__ x0) {
    const int lane = threadIdx.x & 31;
    const int warp = (blockIdx.x * blockDim.x + threadIdx.x) >> 5;
    const int e0 = warp * 32;
    if (e0 >= N_EDGES) return;
    const int e = e0 + lane;
    int d = 0, s = 0; float w = 0.f;
    bool ok = false;
    if (e < N_EDGES) {
        d = ei[N_EDGES + e];
        ok = (g_needed[d] != 0);
        if (ok) { s = ei[e]; w = ew[e]; }
    }
    unsigned mask = __ballot_sync(0xffffffffu, ok);
    while (mask) {
        int b = __ffs(mask) - 1; mask &= (mask - 1);
        int   ss = __shfl_sync(0xffffffffu, s, b);
        int   dd = __shfl_sync(0xffffffffu, d, b);
        float ww = __shfl_sync(0xffffffffu, w, b);
        const float4* xr = reinterpret_cast<const float4*>(x0 + (size_t)ss * GNN_DIM);
        float* ar = g_aggr + (size_t)dd * GNN_DIM;
        #pragma unroll
        for (int i = 0; i < 2; i++) {
            int c = lane + i * 32;
            float4 v = xr[c];
            asm volatile("red.global.add.v4.f32 [%0], {%1,%2,%3,%4};"
                         :: "l"(ar + c * 4), "f"(v.x * ww), "f"(v.y * ww),
                            "f"(v.z * ww), "f"(v.w * ww) : "memory");
        }
    }
}

// ---------------- fold message-passing weights ----------------
__global__ void wc_kernel(const float* __restrict__ Wr, const float* __restrict__ Wn,
                          const float* __restrict__ Wp) {
    int i = blockIdx.x, j = threadIdx.x;
    __shared__ float r[GNN_DIM], nn[GNN_DIM];
    r[j]  = Wr[i * GNN_DIM + j] + (i == j ? 1.f : 0.f);
    nn[j] = Wn[i * GNN_DIM + j];
    __syncthreads();
    float a1 = 0.f, a2 = 0.f;
    #pragma unroll 4
    for (int k = 0; k < GNN_DIM; k++) {
        float wp = Wp[k * GNN_DIM + j];
        a1 += r[k] * wp; a2 += nn[k] * wp;
    }
    g_Wc1[i * GNN_DIM + j] = a1;
    g_Wc2[i * GNN_DIM + j] = a2;
}

__global__ void bc_kernel(const float* __restrict__ bmp, const float* __restrict__ Wp,
                          const float* __restrict__ bpost) {
    int j = threadIdx.x;
    float a = bpost[j];
    #pragma unroll 4
    for (int k = 0; k < GNN_DIM; k++)
        a += bmp[k] * Wp[k * GNN_DIM + j];
    g_bc[j] = a;
}

// ---------------- per-batch-row node transform -> split pert ----------------
__global__ void pert_kernel(const int* __restrict__ idx, const float* __restrict__ x0,
                            const float* __restrict__ fb) {
    constexpr int RPB = 8;
    __shared__ float xr[RPB][GNN_DIM];
    __shared__ float ar[RPB][GNN_DIM];
    __shared__ int   ns[RPB];
    int j = threadIdx.x;
    int b0 = blockIdx.x * RPB;
    if (j < RPB) ns[j] = idx[b0 + j];
    __syncthreads();
    #pragma unroll
    for (int r = 0; r < RPB; r++) {
        int n = ns[r]; int sn = (n < 0) ? 0 : n;
        xr[r][j] = x0[(size_t)sn * GNN_DIM + j];
        ar[r][j] = g_aggr[(size_t)sn * GNN_DIM + j];
    }
    __syncthreads();
    float acc[RPB];
    #pragma unroll
    for (int r = 0; r < RPB; r++) acc[r] = g_bc[j];
    for (int k = 0; k < GNN_DIM; k++) {
        float w1 = g_Wc1[k * GNN_DIM + j];
        float w2 = g_Wc2[k * GNN_DIM + j];
        #pragma unroll
        for (int r = 0; r < RPB; r++)
            acc[r] += xr[r][k] * w1 + ar[r][k] * w2;
    }
    float fbj = fb[j];
    #pragma unroll
    for (int r = 0; r < RPB; r++) {
        float v = (ns[r] >= 0) ? acc[r] : fbj;
        __nv_bfloat16 h, l; split2(v, h, l);
        g_perth[(size_t)(b0 + r) * GNN_DIM + j] = h;
        g_pertl[(size_t)(b0 + r) * GNN_DIM + j] = l;
    }
}

// ---------------- layernorm -> split xn ----------------
__global__ void ln_kernel(const float* __restrict__ hbuf, const float* __restrict__ g,
                          const float* __restrict__ bb) {
    int row = blockIdx.x;
    const float* x = hbuf + (size_t)row * HEAD_DIM;
    int tid = threadIdx.x;   // 128
    float v[4]; float s = 0.f, s2 = 0.f;
    #pragma unroll
    for (int i = 0; i < 4; i++) {
        v[i] = x[tid + i * 128];
        s += v[i]; s2 += v[i] * v[i];
    }
    #pragma unroll
    for (int o = 16; o; o >>= 1) {
        s  += __shfl_down_sync(0xffffffffu, s, o);
        s2 += __shfl_down_sync(0xffffffffu, s2, o);
    }
    __shared__ float ss[4], ss2[4];
    if ((tid & 31) == 0) { ss[tid >> 5] = s; ss2[tid >> 5] = s2; }
    __syncthreads();
    s  = ss[0] + ss[1] + ss[2] + ss[3];
    s2 = ss2[0] + ss2[1] + ss2[2] + ss2[3];
    float mu  = s * (1.f / HEAD_DIM);
    float var = s2 * (1.f / HEAD_DIM) - mu * mu;
    float rs  = rsqrtf(var + 1e-5f);
    #pragma unroll
    for (int i = 0; i < 4; i++) {
        int j = tid + i * 128;
        float o = (v[i] - mu) * rs * g[j] + bb[j];
        __nv_bfloat16 hh, ll; split2(o, hh, ll);
        g_xnh[(size_t)row * HEAD_DIM + j] = hh;
        g_xnl[(size_t)row * HEAD_DIM + j] = ll;
    }
}

// ---------------- fp32 -> bf16 hi/lo split (weights & h) ----------------
__global__ void split_kernel(const float* __restrict__ src,
                             __nv_bfloat16* __restrict__ dh,
                             __nv_bfloat16* __restrict__ dl, int n4) {
    int stride = gridDim.x * blockDim.x;
    for (int i = blockIdx.x * blockDim.x + threadIdx.x; i < n4; i += stride) {
        float4 v = reinterpret_cast<const float4*>(src)[i];
        __nv_bfloat16 h0, l0, h1, l1, h2, l2, h3, l3;
        split2(v.x, h0, l0); split2(v.y, h1, l1);
        split2(v.z, h2, l2); split2(v.w, h3, l3);
        __nv_bfloat162* ph = reinterpret_cast<__nv_bfloat162*>(dh) + i * 2;
        __nv_bfloat162* pl = reinterpret_cast<__nv_bfloat162*>(dl) + i * 2;
        ph[0] = __nv_bfloat162{h0, h1}; ph[1] = __nv_bfloat162{h2, h3};
        pl[0] = __nv_bfloat162{l0, l1}; pl[1] = __nv_bfloat162{l2, l3};
    }
}

// ================= bf16x3 tensor-core GEMM =================
// C[M,N] = A[M,K] @ B with A = Ah+Al, B = Bh+Bl (bf16 splits).
// D += Ah*Bh + Al*Bh + Ah*Bl  (lo*lo dropped, ~2^-18 relative).
// Block 128x128x32, 8 warps (2x4), warp tile 64x32, m16n8k16 bf16.
// TRANSB: B source is [N,K] (out_emb); else [K,N]. N ragged only w/ TRANSB.
constexpr int BM = 128, BN = 128, BK = 32;
constexpr int ASTR = BK + 8;        // 40  ([m][k] & [n][k] tiles)
constexpr int BSTR = BN + 8;        // 136 ([k][n] tiles)
constexpr int TILE_E = 5120;        // elems per stage per array (max of layouts)
constexpr int SMEM_BYTES = 4 * 2 * TILE_E * 2;   // 4 arrays * 2 stages * bf16

template<bool TRANSB>
__device__ __forceinline__ void load_stage(
    __nv_bfloat16* sm, int stage, int k0,
    const __nv_bfloat16* Ah, const __nv_bfloat16* Al,
    const __nv_bfloat16* Bh, const __nv_bfloat16* Bl,
    int N, int K, int crow, int ccol, int tid)
{
    __nv_bfloat16* As_h = sm + stage * TILE_E;
    __nv_bfloat16* As_l = sm + 2 * TILE_E + stage * TILE_E;
    __nv_bfloat16* Bs_h = sm + 4 * TILE_E + stage * TILE_E;
    __nv_bfloat16* Bs_l = sm + 6 * TILE_E + stage * TILE_E;
    #pragma unroll
    for (int i = 0; i < 2; i++) {
        int q = tid + i * 256;
        int row = q >> 2, c8 = (q & 3) * 8;
        size_t goff = (size_t)(crow + row) * K + k0 + c8;
        uint32_t soff = row * ASTR + c8;
        cp16(smem_u32(As_h + soff), Ah + goff, true);
        cp16(smem_u32(As_l + soff), Al + goff, true);
    }
    if (!TRANSB) {
        #pragma unroll
        for (int i = 0; i < 2; i++) {
            int q = tid + i * 256;
            int row = q >> 4, c8 = (q & 15) * 8;
            size_t goff = (size_t)(k0 + row) * N + ccol + c8;
            uint32_t soff = row * BSTR + c8;
            cp16(smem_u32(Bs_h + soff), Bh + goff, true);
            cp16(smem_u32(Bs_l + soff), Bl + goff, true);
        }
    } else {
        #pragma unroll
        for (int i = 0; i < 2; i++) {
            int q = tid + i * 256;
            int row = q >> 2, c8 = (q & 3) * 8;
            bool ok = (ccol + row) < N;
            size_t goff = ok ? ((size_t)(ccol + row) * K + k0 + c8) : 0;
            uint32_t soff = row * ASTR + c8;
            cp16(smem_u32(Bs_h + soff), Bh + goff, ok);
            cp16(smem_u32(Bs_l + soff), Bl + goff, ok);
        }
    }
}

// load 4 A fragments (4 m-tiles) for k-offset kk
__device__ __forceinline__ void load_afrag(uint32_t a[4][4], const __nv_bfloat16* As,
                                           int warpM, int lane, int kk) {
    int lrow = warpM + (lane & 15);
    int lcol = kk + ((lane >> 4) << 3);
    #pragma unroll
    for (int mt = 0; mt < 4; mt++)
        ldm_x4(a[mt], smem_u32(As + (lrow + mt * 16) * ASTR + lcol));
}

template<bool TRANSB>
__device__ __forceinline__ void load_bfrag(uint32_t b[4][2], const __nv_bfloat16* Bs,
                                           int warpN, int lane, int kk) {
    int j = lane >> 3, r8 = lane & 7;
    if (!TRANSB) {
        int krow = kk + r8 + ((j & 1) << 3);
        #pragma unroll
        for (int np = 0; np < 2; np++) {
            int ncol = warpN + np * 16 + ((j >> 1) << 3);
            uint32_t r[4];
            ldm_x4_t(r, smem_u32(Bs + krow * BSTR + ncol));
            b[np * 2][0] = r[0]; b[np * 2][1] = r[1];
            b[np * 2 + 1][0] = r[2]; b[np * 2 + 1][1] = r[3];
        }
    } else {
        int kcol = kk + ((j & 1) << 3);
        #pragma unroll
        for (int np = 0; np < 2; np++) {
            int nrow = warpN + np * 16 + r8 + ((j >> 1) << 3);
            uint32_t r[4];
            ldm_x4(r, smem_u32(Bs + nrow * ASTR + kcol));
            b[np * 2][0] = r[0]; b[np * 2][1] = r[1];
            b[np * 2 + 1][0] = r[2]; b[np * 2 + 1][1] = r[3];
        }
    }
}

template<bool TRANSB, bool BIAS, bool GELU, bool SPLITOUT, bool RESID>
__global__ void __launch_bounds__(256, 1) gemm_bf3(
    int M, int N, int K,
    const __nv_bfloat16* __restrict__ Ah, const __nv_bfloat16* __restrict__ Al,
    const __nv_bfloat16* __restrict__ Bh, const __nv_bfloat16* __restrict__ Bl,
    const float* __restrict__ bias, float* __restrict__ C,
    __nv_bfloat16* __restrict__ Oh, __nv_bfloat16* __restrict__ Ol)
{
    extern __shared__ __nv_bfloat16 sm[];
    const int tid  = threadIdx.x;
    const int lane = tid & 31;
    const int warp = tid >> 5;
    const int crow = blockIdx.y * BM;
    const int ccol = blockIdx.x * BN;
    const int warpM = (warp >> 2) * 64;
    const int warpN = (warp & 3) * 32;
    const int r = lane >> 2, c = lane & 3;

    float acc[4][4][4];
    #pragma unroll
    for (int mt = 0; mt < 4; mt++)
        #pragma unroll
        for (int nt = 0; nt < 4; nt++)
            #pragma unroll
            for (int i = 0; i < 4; i++) acc[mt][nt][i] = 0.f;

    const int KT = K / BK;
    load_stage<TRANSB>(sm, 0, 0, Ah, Al, Bh, Bl, N, K, crow, ccol, tid);
    asm volatile("cp.async.commit_group;" ::: "memory");

    for (int kt = 0; kt < KT; kt++) {
        if (kt + 1 < KT) {
            load_stage<TRANSB>(sm, (kt + 1) & 1, (kt + 1) * BK,
                               Ah, Al, Bh, Bl, N, K, crow, ccol, tid);
            asm volatile("cp.async.commit_group;" ::: "memory");
            asm volatile("cp.async.wait_group 1;" ::: "memory");
        } else {
            asm volatile("cp.async.wait_group 0;" ::: "memory");
        }
        __syncthreads();

        const int st = kt & 1;
        const __nv_bfloat16* As_h = sm + st * TILE_E;
        const __nv_bfloat16* As_l = sm + 2 * TILE_E + st * TILE_E;
        const __nv_bfloat16* Bs_h = sm + 4 * TILE_E + st * TILE_E;
        const __nv_bfloat16* Bs_l = sm + 6 * TILE_E + st * TILE_E;

        #pragma unroll
        for (int ks = 0; ks < 2; ks++) {
            const int kk = ks * 16;
            uint32_t ah[4][4], al[4][4], bh[4][2], bl[4][2];
            load_afrag(ah, As_h, warpM, lane, kk);
            load_bfrag<TRANSB>(bh, Bs_h, warpN, lane, kk);
            #pragma unroll
            for (int mt = 0; mt < 4; mt++)
                #pragma unroll
                for (int nt = 0; nt < 4; nt++)
                    MMA_BF16(acc[mt][nt], ah[mt], bh[nt]);
            load_afrag(al, As_l, warpM, lane, kk);
            #pragma unroll
            for (int mt = 0; mt < 4; mt++)
                #pragma unroll
                for (int nt = 0; nt < 4; nt++)
                    MMA_BF16(acc[mt][nt], al[mt], bh[nt]);
            load_bfrag<TRANSB>(bl, Bs_l, warpN, lane, kk);
            #pragma unroll
            for (int mt = 0; mt < 4; mt++)
                #pragma unroll
                for (int nt = 0; nt < 4; nt++)
                    MMA_BF16(acc[mt][nt], ah[mt], bl[nt]);
        }
        __syncthreads();
    }

    // ---- epilogue ----
    #pragma unroll
    for (int mt = 0; mt < 4; mt++) {
        #pragma unroll
        for (int nt = 0; nt < 4; nt++) {
            int m0 = crow + warpM + mt * 16;
            int n0 = ccol + warpN + nt * 8;
            #pragma unroll
            for (int half = 0; half < 2; half++) {
                int m = m0 + r + half * 8;
                int n = n0 + c * 2;
                if (n >= N) continue;       // pairs stay in-bounds (N even)
                float v0 = acc[mt][nt][half * 2 + 0];
                float v1 = acc[mt][nt][half * 2 + 1];
                if (BIAS) { v0 += bias[n]; v1 += bias[n + 1]; }
                if (GELU) { v0 = gelu_exact(v0); v1 = gelu_exact(v1); }
                if (SPLITOUT) {
                    __nv_bfloat16 h0, l0, h1, l1;
                    split2(v0, h0, l0); split2(v1, h1, l1);
                    *reinterpret_cast<__nv_bfloat162*>(Oh + (size_t)m * N + n) =
                        __nv_bfloat162{h0, h1};
                    *reinterpret_cast<__nv_bfloat162*>(Ol + (size_t)m * N + n) =
                        __nv_bfloat162{l0, l1};
                } else {
                    float2* p = reinterpret_cast<float2*>(C + (size_t)m * N + n);
                    if (RESID) { float2 o = *p; v0 += o.x; v1 += o.y; }
                    *p = make_float2(v0, v1);
                }
            }
        }
    }
}

// ---------------- launch ----------------
extern "C" void kernel_launch(void* const* d_in, const int* in_sizes, int n_in,
                              void* d_out, int out_size) {
    const int*   node_idx  = (const int*)  d_in[0];
    const int*   edge_idx  = (const int*)  d_in[1];
    const float* edge_w    = (const float*)d_in[2];
    const float* frozen    = (const float*)d_in[3];
    const float* W_root    = (const float*)d_in[4];
    const float* W_nbr     = (const float*)d_in[5];
    const float* b_mp      = (const float*)d_in[6];
    const float* W_post    = (const float*)d_in[7];
    const float* b_post    = (const float*)d_in[8];
    const float* fallback  = (const float*)d_in[9];
    const float* W_in      = (const float*)d_in[10];
    const float* b_in      = (const float*)d_in[11];
    const float* ln_g      = (const float*)d_in[12];
    const float* ln_b      = (const float*)d_in[13];
    const float* W1        = (const float*)d_in[14];
    const float* b1        = (const float*)d_in[15];
    const float* W2        = (const float*)d_in[16];
    const float* W_bil     = (const float*)d_in[17];
    const float* out_emb   = (const float*)d_in[18];
    float*       logits    = (float*)d_out;

    float *p_h;
    cudaGetSymbolAddress((void**)&p_h, g_h);
    __nv_bfloat16 *p_perth, *p_pertl, *p_xnh, *p_xnl, *p_acth, *p_actl;
    __nv_bfloat16 *p_hsh, *p_hsl, *p_projh, *p_projl;
    __nv_bfloat16 *p_Winh, *p_Winl, *p_W1h, *p_W1l, *p_W2h, *p_W2l;
    __nv_bfloat16 *p_bilh, *p_bill, *p_oeh, *p_oel;
    cudaGetSymbolAddress((void**)&p_perth, g_perth);
    cudaGetSymbolAddress((void**)&p_pertl, g_pertl);
    cudaGetSymbolAddress((void**)&p_xnh,  g_xnh);
    cudaGetSymbolAddress((void**)&p_xnl,  g_xnl);
    cudaGetSymbolAddress((void**)&p_acth, g_acth);
    cudaGetSymbolAddress((void**)&p_actl, g_actl);
    cudaGetSymbolAddress((void**)&p_hsh,  g_hsh);
    cudaGetSymbolAddress((void**)&p_hsl,  g_hsl);
    cudaGetSymbolAddress((void**)&p_projh, g_projh);
    cudaGetSymbolAddress((void**)&p_projl, g_projl);
    cudaGetSymbolAddress((void**)&p_Winh, g_Winh);
    cudaGetSymbolAddress((void**)&p_Winl, g_Winl);
    cudaGetSymbolAddress((void**)&p_W1h,  g_W1h);
    cudaGetSymbolAddress((void**)&p_W1l,  g_W1l);
    cudaGetSymbolAddress((void**)&p_W2h,  g_W2h);
    cudaGetSymbolAddress((void**)&p_W2l,  g_W2l);
    cudaGetSymbolAddress((void**)&p_bilh, g_bilh);
    cudaGetSymbolAddress((void**)&p_bill, g_bill);
    cudaGetSymbolAddress((void**)&p_oeh,  g_oeh);
    cudaGetSymbolAddress((void**)&p_oel,  g_oel);

    // raise dynamic-smem limit for all gemm instantiations (idempotent)
    cudaFuncSetAttribute(gemm_bf3<false, true,  true,  false, false>,
                         cudaFuncAttributeMaxDynamicSharedMemorySize, SMEM_BYTES);
    cudaFuncSetAttribute(gemm_bf3<false, true,  true,  true,  false>,
                         cudaFuncAttributeMaxDynamicSharedMemorySize, SMEM_BYTES);
    cudaFuncSetAttribute(gemm_bf3<false, false, false, false, true>,
                         cudaFuncAttributeMaxDynamicSharedMemorySize, SMEM_BYTES);
    cudaFuncSetAttribute(gemm_bf3<false, false, false, true,  false>,
                         cudaFuncAttributeMaxDynamicSharedMemorySize, SMEM_BYTES);
    cudaFuncSetAttribute(gemm_bf3<true,  false, false, false, false>,
                         cudaFuncAttributeMaxDynamicSharedMemorySize, SMEM_BYTES);

    // --- weight splits (bf16 hi/lo) ---
    split_kernel<<<256, 256>>>(W_in,   p_Winh, p_Winl, GNN_DIM * HEAD_DIM / 4);
    split_kernel<<<1024, 256>>>(W1,    p_W1h,  p_W1l,  N_RES * HEAD_DIM * FF_DIM / 4);
    split_kernel<<<1024, 256>>>(W2,    p_W2h,  p_W2l,  N_RES * FF_DIM * HEAD_DIM / 4);
    split_kernel<<<512, 256>>>(W_bil,  p_bilh, p_bill, HEAD_DIM * BIL_DIM / 4);
    split_kernel<<<1024, 256>>>(out_emb, p_oeh, p_oel, N_GENES * HEAD_DIM / 4);

    // --- graph phase ---
    zero_kernel<<<1024, 256>>>();
    mark_kernel<<<(BATCH + 255) / 256, 256>>>(node_idx);
    {
        int warps = (N_EDGES + 31) / 32;
        int blocks = (warps + 7) / 8;
        edge_kernel<<<blocks, 256>>>(edge_idx, edge_w, frozen);
    }
    wc_kernel<<<GNN_DIM, GNN_DIM>>>(W_root, W_nbr, W_post);
    bc_kernel<<<1, GNN_DIM>>>(b_mp, W_post, b_post);
    pert_kernel<<<BATCH / 8, GNN_DIM>>>(node_idx, frozen, fallback);

    // --- dense head ---
    // h = gelu(pert @ W_in + b_in)
    {
        dim3 grid(HEAD_DIM / BN, BATCH / BM);
        gemm_bf3<false, true, true, false, false><<<grid, 256, SMEM_BYTES>>>(
            BATCH, HEAD_DIM, GNN_DIM, p_perth, p_pertl, p_Winh, p_Winl,
            b_in, p_h, nullptr, nullptr);
    }
    for (int i = 0; i < N_RES; i++) {
        ln_kernel<<<BATCH, 128>>>(p_h, ln_g + (size_t)i * HEAD_DIM,
                                  ln_b + (size_t)i * HEAD_DIM);
        dim3 g1(FF_DIM / BN, BATCH / BM);
        gemm_bf3<false, true, true, true, false><<<g1, 256, SMEM_BYTES>>>(
            BATCH, FF_DIM, HEAD_DIM, p_xnh, p_xnl,
            p_W1h + (size_t)i * HEAD_DIM * FF_DIM, p_W1l + (size_t)i * HEAD_DIM * FF_DIM,
            b1 + (size_t)i * FF_DIM, nullptr, p_acth, p_actl);
        dim3 g2(HEAD_DIM / BN, BATCH / BM);
        gemm_bf3<false, false, false, false, true><<<g2, 256, SMEM_BYTES>>>(
            BATCH, HEAD_DIM, FF_DIM, p_acth, p_actl,
            p_W2h + (size_t)i * FF_DIM * HEAD_DIM, p_W2l + (size_t)i * FF_DIM * HEAD_DIM,
            nullptr, p_h, nullptr, nullptr);
    }
    // split h for proj
    split_kernel<<<256, 256>>>(p_h, p_hsh, p_hsl, BATCH * HEAD_DIM / 4);
    // proj = h @ W_bil  (split output)
    {
        dim3 grid(BIL_DIM / BN, BATCH / BM);
        gemm_bf3<false, false, false, true, false><<<grid, 256, SMEM_BYTES>>>(
            BATCH, BIL_DIM, HEAD_DIM, p_hsh, p_hsl, p_bilh, p_bill,
            nullptr, nullptr, p_projh, p_projl);
    }
    // logits = reshape(proj,[B*3,512]) @ out_emb^T
    {
        dim3 grid((N_GENES + BN - 1) / BN, (BATCH * N_CLASSES) / BM);
        gemm_bf3<true, false, false, false, false><<<grid, 256, SMEM_BYTES>>>(
            BATCH * N_CLASSES, N_GENES, HEAD_DIM, p_projh, p_projl, p_oeh, p_oel,
            nullptr, logits, nullptr, nullptr);
    }
}